// round 9
// baseline (speedup 1.0000x reference)
#include <cuda_runtime.h>
#include <cuda_bf16.h>
#include <cstdint>
#include <cstddef>

// TemporalAttention via warp-level bf16 mma.sync (HMMA), warp-specialized:
// warps 0-7 compute QK-projection + softmax, warps 8-15 compute V-projection
// concurrently; attention weights cross via smem. 3-term hi/lo bf16 split.

namespace {
constexpr int kT = 8, kC = 128, kHW = 96 * 96, kPIX = 16, kTHREADS = 512;
constexpr int kSA = 272;                 // row stride in bytes (136 bf16)
// smem regions (bytes)
constexpr int A_HI   = 0;
constexpr int A_LO   = 34816;
constexpr int BQK_HI = 69632;            // aliases: x-transpose scratch
constexpr int BQK_LO = 104448;
constexpr int BV_HI  = 139264;
constexpr int BV_LO  = 174080;
constexpr int BIAS   = 208896;           // 256 floats: bq | bk | bv
constexpr int SSM    = 209920;           // attn 128*8 fp32
constexpr int kSMEM  = 214016;
// out staging aliases A region (max idx 16411 floats = 65644 B < 69632)
}

__device__ __forceinline__ uint32_t s2u(const void* p) {
    uint32_t a;
    asm("{ .reg .u64 t; cvta.to.shared.u64 t, %1; cvt.u32.u64 %0, t; }"
        : "=r"(a) : "l"(p));
    return a;
}
__device__ __forceinline__ void ldsm4(uint32_t& r0, uint32_t& r1, uint32_t& r2,
                                      uint32_t& r3, uint32_t addr) {
    asm volatile("ldmatrix.sync.aligned.m8n8.x4.shared.b16 {%0,%1,%2,%3}, [%4];"
                 : "=r"(r0), "=r"(r1), "=r"(r2), "=r"(r3) : "r"(addr));
}
__device__ __forceinline__ void mma16816(float* d, uint32_t a0, uint32_t a1,
                                         uint32_t a2, uint32_t a3,
                                         uint32_t b0, uint32_t b1) {
    asm volatile(
        "mma.sync.aligned.m16n8k16.row.col.f32.bf16.bf16.f32 "
        "{%0,%1,%2,%3}, {%4,%5,%6,%7}, {%8,%9}, {%0,%1,%2,%3};"
        : "+f"(d[0]), "+f"(d[1]), "+f"(d[2]), "+f"(d[3])
        : "r"(a0), "r"(a1), "r"(a2), "r"(a3), "r"(b0), "r"(b1));
}
__device__ __forceinline__ void split2(float v0, float v1, uint32_t& hw,
                                       uint32_t& lw) {
    __nv_bfloat16 h0 = __float2bfloat16(v0), h1 = __float2bfloat16(v1);
    float r0 = v0 - __bfloat162float(h0), r1 = v1 - __bfloat162float(h1);
    __nv_bfloat16 l0 = __float2bfloat16(r0), l1 = __float2bfloat16(r1);
    hw = ((uint32_t)__bfloat16_as_ushort(h1) << 16) | __bfloat16_as_ushort(h0);
    lw = ((uint32_t)__bfloat16_as_ushort(l1) << 16) | __bfloat16_as_ushort(l0);
}

// one 128(m) x 128(n) x 128(k) 3-term split GEMM; warp gw owns rows gw*16..+15
__device__ __forceinline__ void do_gemm(uint32_t aHi, uint32_t aLo,
                                        uint32_t bHi, uint32_t bLo,
                                        int lane, int gw, float d[16][4]) {
#pragma unroll
    for (int nt = 0; nt < 16; ++nt)
#pragma unroll
        for (int r = 0; r < 4; ++r) d[nt][r] = 0.f;

    const uint32_t abyte = (uint32_t)(gw * 16 + (lane & 15)) * kSA +
                           ((lane >> 4) * 16);
    const int bro = (lane & 7) + (((lane >> 4) & 1) * 8);
    const uint32_t bkh = (uint32_t)(((lane >> 3) & 1) * 16);

#pragma unroll
    for (int ks = 0; ks < 8; ++ks) {
        uint32_t ao = abyte + ks * 32;
        uint32_t ah0, ah1, ah2, ah3, al0, al1, al2, al3;
        ldsm4(ah0, ah1, ah2, ah3, aHi + ao);
        ldsm4(al0, al1, al2, al3, aLo + ao);
#pragma unroll
        for (int ntp = 0; ntp < 8; ++ntp) {
            uint32_t bo = (uint32_t)(ntp * 16 + bro) * kSA + ks * 32 + bkh;
            uint32_t h0, h1, h2, h3, l0, l1, l2, l3;
            ldsm4(h0, h1, h2, h3, bHi + bo);
            ldsm4(l0, l1, l2, l3, bLo + bo);
            mma16816(d[2 * ntp], ah0, ah1, ah2, ah3, h0, h1);
            mma16816(d[2 * ntp], al0, al1, al2, al3, h0, h1);
            mma16816(d[2 * ntp], ah0, ah1, ah2, ah3, l0, l1);
            mma16816(d[2 * ntp + 1], ah0, ah1, ah2, ah3, h2, h3);
            mma16816(d[2 * ntp + 1], al0, al1, al2, al3, h2, h3);
            mma16816(d[2 * ntp + 1], ah0, ah1, ah2, ah3, l2, l3);
        }
    }
}

__global__ __launch_bounds__(kTHREADS, 1)
void ta_mma(const float* __restrict__ x,
            const float* __restrict__ Wq, const float* __restrict__ bq,
            const float* __restrict__ Wk, const float* __restrict__ bk,
            const float* __restrict__ Wv, const float* __restrict__ bv,
            float* __restrict__ out)
{
    extern __shared__ char smem[];
    const uint32_t sb = s2u(smem);
    float* scratch = (float*)(smem + BQK_HI);
    float* outst   = (float*)(smem);
    float* bias_sm = (float*)(smem + BIAS);
    float* Ssm     = (float*)(smem + SSM);

    const int tid = threadIdx.x, wid = tid >> 5, lane = tid & 31;
    const int b = blockIdx.y, pix0 = blockIdx.x * kPIX;

    // ---- phase 1: x -> scratch (coalesced reads, rotated layout) ----------
    const float* xb = x + (size_t)b * (kT * kC * kHW) + pix0;
    for (int i = tid; i < kT * kC * kPIX; i += kTHREADS) {
        int p = i & 15, tc = i >> 4;            // tc = t*128 + c
        int c = tc & 127, t = tc >> 7;
        scratch[tc * 16 + ((p + (c >> 1)) & 15) + t * 4] =
            xb[(size_t)tc * kHW + p];
    }
    // ---- Bv staging + bias (scratch-free regions) -------------------------
    for (int i = tid; i < 128 * 64; i += kTHREADS) {
        int n = i >> 6, cp = i & 63;
        float2 v = *(const float2*)(Wv + n * kC + cp * 2);
        uint32_t hw, lw;
        split2(v.x, v.y, hw, lw);
        *(uint32_t*)(smem + BV_HI + n * kSA + cp * 4) = hw;
        *(uint32_t*)(smem + BV_LO + n * kSA + cp * 4) = lw;
    }
    if (tid < 256)
        bias_sm[tid] = (tid < 64) ? bq[tid]
                     : (tid < 128) ? bk[tid - 64] : bv[tid - 128];
    __syncthreads();

    // ---- phase 2: scratch -> A hi/lo (bf16, transposed to [m][c]) ---------
    for (int i = tid; i < 128 * 64; i += kTHREADS) {
        int cp = i & 63, m = i >> 6;
        int t = m & 7, p = m >> 3;
        int base = (t * 128 + 2 * cp) * 16 + t * 4;
        int prot = (p + cp) & 15;
        float f0 = scratch[base + prot];
        float f1 = scratch[base + 16 + prot];
        uint32_t hw, lw;
        split2(f0, f1, hw, lw);
        *(uint32_t*)(smem + A_HI + m * kSA + cp * 4) = hw;
        *(uint32_t*)(smem + A_LO + m * kSA + cp * 4) = lw;
    }
    __syncthreads();

    // ---- Bqk staging (overwrites scratch) ---------------------------------
    for (int i = tid; i < 128 * 64; i += kTHREADS) {
        int n = i >> 6, cp = i & 63;
        const float* src = (n < 64) ? (Wq + n * kC) : (Wk + (n - 64) * kC);
        float2 v = *(const float2*)(src + cp * 2);
        uint32_t hw, lw;
        split2(v.x, v.y, hw, lw);
        *(uint32_t*)(smem + BQK_HI + n * kSA + cp * 4) = hw;
        *(uint32_t*)(smem + BQK_LO + n * kSA + cp * 4) = lw;
    }
    __syncthreads();

    const int l4 = lane & 3, lg = lane >> 2;    // lg = t (fragment row)
    const int gw = wid & 7;                     // GEMM row-block id
    float d[16][4];

    if (wid < 8) {
        // ================= QK warps: GEMM1 + softmax =======================
        do_gemm(sb + A_HI, sb + A_LO, sb + BQK_HI, sb + BQK_LO, lane, gw, d);

        // bias in-place: nt<8 -> Q (+bq), nt>=8 -> K (+bk)
#pragma unroll
        for (int nt = 0; nt < 16; ++nt) {
            int c = (nt & 7) * 8 + l4 * 2;
            float b0 = bias_sm[(nt < 8 ? 0 : 64) + c];
            float b1 = bias_sm[(nt < 8 ? 0 : 64) + c + 1];
            d[nt][0] += b0; d[nt][1] += b1;
            d[nt][2] += b0; d[nt][3] += b1;
        }

#pragma unroll
        for (int pi = 0; pi < 2; ++pi) {
            float sc[8];
#pragma unroll
            for (int s = 0; s < 8; ++s) {
                int src = s * 4 + l4;
                float a = 0.f;
#pragma unroll
                for (int nt = 0; nt < 8; ++nt)
#pragma unroll
                    for (int j = 0; j < 2; ++j)
                        a += d[nt][pi * 2 + j] *
                             __shfl_sync(0xffffffffu, d[8 + nt][pi * 2 + j], src);
                a += __shfl_xor_sync(0xffffffffu, a, 1);
                a += __shfl_xor_sync(0xffffffffu, a, 2);
                sc[s] = a * 0.125f;             // 1/sqrt(64)
            }
            float mx = sc[0];
#pragma unroll
            for (int s = 1; s < 8; ++s) mx = fmaxf(mx, sc[s]);
            float sum = 0.f, e[8];
#pragma unroll
            for (int s = 0; s < 8; ++s) { e[s] = __expf(sc[s] - mx); sum += e[s]; }
            float inv = 1.f / sum;
            if (l4 == 0) {
                int p = gw * 2 + pi;
#pragma unroll
                for (int s = 0; s < 8; ++s)
                    Ssm[(p * 8 + lg) * 8 + s] = e[s] * inv;
            }
        }
    } else {
        // ================= V warps: GEMM2 ==================================
        do_gemm(sb + A_HI, sb + A_LO, sb + BV_HI, sb + BV_LO, lane, gw, d);
    }
    __syncthreads();    // Ssm ready; both GEMMs done -> A region reusable

    if (wid >= 8) {
        // ---- mix attn@V + bv, stage rotated for coalesced stores ----------
        const int p0 = gw * 2, p1 = gw * 2 + 1;
        float attn0[8], attn1[8];
#pragma unroll
        for (int s = 0; s < 8; ++s) {
            attn0[s] = Ssm[(p0 * 8 + lg) * 8 + s];
            attn1[s] = Ssm[(p1 * 8 + lg) * 8 + s];
        }
#pragma unroll
        for (int nt = 0; nt < 16; ++nt)
#pragma unroll
            for (int j = 0; j < 2; ++j) {
                int c = nt * 8 + l4 * 2 + j;
                float o0 = bias_sm[128 + c], o1 = o0;
#pragma unroll
                for (int s = 0; s < 8; ++s) {
                    int src = s * 4 + l4;
                    o0 += attn0[s] * __shfl_sync(0xffffffffu, d[nt][j], src);
                    o1 += attn1[s] * __shfl_sync(0xffffffffu, d[nt][2 + j], src);
                }
                int base = (lg * 128 + c) * 16 + lg * 4;
                int rot = (c >> 1) & 15;
                outst[base + ((p0 + rot) & 15)] = o0;
                outst[base + ((p1 + rot) & 15)] = o1;
            }
    }
    __syncthreads();

    // ---- coalesced gmem store: out[b,t,e,pix0+p] --------------------------
    {
        float* ob = out + (size_t)b * (kT * kC * kHW) + pix0;
        const int sp = tid & 15, g = tid >> 4;  // g in [0,32)
#pragma unroll 4
        for (int it = 0; it < 32; ++it) {
            int q = it * 32 + g;                // t*128 + e
            int t = q >> 7, c = q & 127;
            ob[(size_t)q * kHW + sp] =
                outst[q * 16 + ((sp + (c >> 1)) & 15) + t * 4];
        }
    }
}

extern "C" void kernel_launch(void* const* d_in, const int* in_sizes, int n_in,
                              void* d_out, int out_size)
{
    const float* x  = (const float*)d_in[0];
    const float* Wq = (const float*)d_in[1];
    const float* bq = (const float*)d_in[2];
    const float* Wk = (const float*)d_in[3];
    const float* bk = (const float*)d_in[4];
    const float* Wv = (const float*)d_in[5];
    const float* bv = (const float*)d_in[6];
    float* out = (float*)d_out;

    const int B = in_sizes[0] / (kT * kC * kHW);
    cudaFuncSetAttribute(ta_mma, cudaFuncAttributeMaxDynamicSharedMemorySize,
                         kSMEM);
    dim3 grid(kHW / kPIX, B);
    ta_mma<<<grid, kTHREADS, kSMEM>>>(x, Wq, bq, Wk, bk, Wv, bv, out);
}

// round 10
// speedup vs baseline: 1.7931x; 1.7931x over previous
#include <cuda_runtime.h>
#include <cuda_bf16.h>
#include <cstdint>
#include <cstddef>

// TemporalAttention — persistent-CTA bf16 mma.sync version.
// 152 CTAs x 256 threads; each CTA loops over 8-pixel tiles (m = p*8+t, 64 rows).
// Weights staged (hi/lo bf16 split) ONCE per CTA; next tile's x prefetched into
// registers during current tile's GEMMs. Warps 0-3: QK GEMM + softmax;
// warps 4-7: V GEMM + attn-mix. 3-term hi/lo split, fp32 accum.

namespace {
constexpr int kT = 8, kC = 128, kHW = 9216, kPIX = 8, kTHREADS = 256;
constexpr int kGRID = 152;
constexpr int kSA = 272;                 // B/A row stride in bytes (136 bf16)
// smem byte offsets
constexpr int BQK_HI = 0;                // 128 x 272
constexpr int BQK_LO = 34816;
constexpr int BV_HI  = 69632;
constexpr int BV_LO  = 104448;
constexpr int A_HI   = 139264;           // 64 x 272
constexpr int A_LO   = 156672;
constexpr int BIAS   = 174080;           // 256 floats
constexpr int SSM    = 175104;           // 8px * 8 * 8 floats
constexpr int OUTS   = 177152;           // outst (10-slot rows) / fp32 scratch
constexpr int kSMEM  = 218176;           // OUTS + 41024
}

__device__ __forceinline__ uint32_t s2u(const void* p) {
    uint32_t a;
    asm("{ .reg .u64 t; cvta.to.shared.u64 t, %1; cvt.u32.u64 %0, t; }"
        : "=r"(a) : "l"(p));
    return a;
}
__device__ __forceinline__ void ldsm4(uint32_t& r0, uint32_t& r1, uint32_t& r2,
                                      uint32_t& r3, uint32_t addr) {
    asm volatile("ldmatrix.sync.aligned.m8n8.x4.shared.b16 {%0,%1,%2,%3}, [%4];"
                 : "=r"(r0), "=r"(r1), "=r"(r2), "=r"(r3) : "r"(addr));
}
__device__ __forceinline__ void mma16816(float* d, uint32_t a0, uint32_t a1,
                                         uint32_t a2, uint32_t a3,
                                         uint32_t b0, uint32_t b1) {
    asm volatile(
        "mma.sync.aligned.m16n8k16.row.col.f32.bf16.bf16.f32 "
        "{%0,%1,%2,%3}, {%4,%5,%6,%7}, {%8,%9}, {%0,%1,%2,%3};"
        : "+f"(d[0]), "+f"(d[1]), "+f"(d[2]), "+f"(d[3])
        : "r"(a0), "r"(a1), "r"(a2), "r"(a3), "r"(b0), "r"(b1));
}
__device__ __forceinline__ void split2(float v0, float v1, uint32_t& hw,
                                       uint32_t& lw) {
    __nv_bfloat16 h0 = __float2bfloat16(v0), h1 = __float2bfloat16(v1);
    float r0 = v0 - __bfloat162float(h0), r1 = v1 - __bfloat162float(h1);
    __nv_bfloat16 l0 = __float2bfloat16(r0), l1 = __float2bfloat16(r1);
    hw = ((uint32_t)__bfloat16_as_ushort(h1) << 16) | __bfloat16_as_ushort(h0);
    lw = ((uint32_t)__bfloat16_as_ushort(l1) << 16) | __bfloat16_as_ushort(l0);
}

// 64(m-slice: rows gw*16..+15) x 128(n) x 128(k) 3-term split GEMM (R8-proven)
__device__ __forceinline__ void do_gemm(uint32_t aHi, uint32_t aLo,
                                        uint32_t bHi, uint32_t bLo,
                                        int lane, int gw, float d[16][4]) {
#pragma unroll
    for (int nt = 0; nt < 16; ++nt)
#pragma unroll
        for (int r = 0; r < 4; ++r) d[nt][r] = 0.f;

    const uint32_t abyte = (uint32_t)(gw * 16 + (lane & 15)) * kSA +
                           ((lane >> 4) * 16);
    const int bro = (lane & 7) + (((lane >> 4) & 1) * 8);
    const uint32_t bkh = (uint32_t)(((lane >> 3) & 1) * 16);

#pragma unroll
    for (int ks = 0; ks < 8; ++ks) {
        uint32_t ao = abyte + ks * 32;
        uint32_t ah0, ah1, ah2, ah3, al0, al1, al2, al3;
        ldsm4(ah0, ah1, ah2, ah3, aHi + ao);
        ldsm4(al0, al1, al2, al3, aLo + ao);
#pragma unroll
        for (int ntp = 0; ntp < 8; ++ntp) {
            uint32_t bo = (uint32_t)(ntp * 16 + bro) * kSA + ks * 32 + bkh;
            uint32_t h0, h1, h2, h3, l0, l1, l2, l3;
            ldsm4(h0, h1, h2, h3, bHi + bo);
            ldsm4(l0, l1, l2, l3, bLo + bo);
            mma16816(d[2 * ntp], ah0, ah1, ah2, ah3, h0, h1);
            mma16816(d[2 * ntp + 1], ah0, ah1, ah2, ah3, h2, h3);
            mma16816(d[2 * ntp], al0, al1, al2, al3, h0, h1);
            mma16816(d[2 * ntp + 1], al0, al1, al2, al3, h2, h3);
            mma16816(d[2 * ntp], ah0, ah1, ah2, ah3, l0, l1);
            mma16816(d[2 * ntp + 1], ah0, ah1, ah2, ah3, l2, l3);
        }
    }
}

__global__ __launch_bounds__(kTHREADS, 1)
void ta_pers(const float* __restrict__ x,
             const float* __restrict__ Wq, const float* __restrict__ bq,
             const float* __restrict__ Wk, const float* __restrict__ bk,
             const float* __restrict__ Wv, const float* __restrict__ bv,
             float* __restrict__ out, int total)
{
    extern __shared__ char smem[];
    const uint32_t sb = s2u(smem);
    float* scratch = (float*)(smem + OUTS);
    float* outst   = (float*)(smem + OUTS);
    float* bias_sm = (float*)(smem + BIAS);
    float* Ssm     = (float*)(smem + SSM);

    const int tid = threadIdx.x, wid = tid >> 5, lane = tid & 31;
    const int l4 = lane & 3, lg = lane >> 2;
    const int p8 = tid & 7, tcb = tid >> 3;       // x-load pixel / tc-group
    const int cta = blockIdx.x;

    // ---- prefetch first tile's x into registers --------------------------
    float xr[32];
    if (cta < total) {
        const float* xb = x + (size_t)(cta / 1152) * (kT * kC * kHW) +
                          (size_t)(cta % 1152) * kPIX;
#pragma unroll
        for (int j = 0; j < 32; ++j)
            xr[j] = xb[(size_t)(j * 32 + tcb) * kHW + p8];
    }

    // ---- weights hi/lo staged ONCE ---------------------------------------
    for (int i = tid; i < 128 * 64; i += kTHREADS) {
        int n = i >> 6, cp = i & 63;
        const float* src = (n < 64) ? (Wq + n * kC) : (Wk + (n - 64) * kC);
        float2 v = *(const float2*)(src + cp * 2);
        uint32_t hw, lw;
        split2(v.x, v.y, hw, lw);
        *(uint32_t*)(smem + BQK_HI + n * kSA + cp * 4) = hw;
        *(uint32_t*)(smem + BQK_LO + n * kSA + cp * 4) = lw;
    }
    for (int i = tid; i < 128 * 64; i += kTHREADS) {
        int n = i >> 6, cp = i & 63;
        float2 v = *(const float2*)(Wv + n * kC + cp * 2);
        uint32_t hw, lw;
        split2(v.x, v.y, hw, lw);
        *(uint32_t*)(smem + BV_HI + n * kSA + cp * 4) = hw;
        *(uint32_t*)(smem + BV_LO + n * kSA + cp * 4) = lw;
    }
    bias_sm[tid] = (tid < 64) ? bq[tid]
                 : (tid < 128) ? bk[tid - 64] : bv[tid - 128];
    __syncthreads();

    // ======================= persistent tile loop ==========================
    for (int tt = cta; tt < total; tt += kGRID) {
        // ---- phase 1: prefetched regs -> fp32 scratch (rotated) ----------
#pragma unroll
        for (int j = 0; j < 32; ++j) {
            int tc = j * 32 + tcb;
            int cp = (tc & 127) >> 1;
            scratch[tc * 8 + ((p8 + cp + (cp >> 3)) & 7)] = xr[j];
        }
        // ---- issue next tile's LDGs (retire under this tile's GEMMs) -----
        {
            int nxt = tt + kGRID;
            if (nxt < total) {
                const float* xb = x + (size_t)(nxt / 1152) * (kT * kC * kHW) +
                                  (size_t)(nxt % 1152) * kPIX;
#pragma unroll
                for (int j = 0; j < 32; ++j)
                    xr[j] = xb[(size_t)(j * 32 + tcb) * kHW + p8];
            }
        }
        __syncthreads();

        // ---- phase 2: scratch -> A hi/lo (bf16, [m][c]) ------------------
#pragma unroll
        for (int k = 0; k < 16; ++k) {
            int i = tid + k * 256;
            int cp = i & 63, m = i >> 6;          // m in [0,64)
            int t = m & 7, pp = m >> 3;
            int slot = (pp + cp + (cp >> 3)) & 7;
            float f0 = scratch[(t * 128 + 2 * cp) * 8 + slot];
            float f1 = scratch[(t * 128 + 2 * cp + 1) * 8 + slot];
            uint32_t hw, lw;
            split2(f0, f1, hw, lw);
            *(uint32_t*)(smem + A_HI + m * kSA + cp * 4) = hw;
            *(uint32_t*)(smem + A_LO + m * kSA + cp * 4) = lw;
        }
        __syncthreads();

        // ---- GEMMs (warp-specialized by n-half) --------------------------
        const int gw = wid & 3;
        float d[16][4];
        if (wid < 4) {
            do_gemm(sb + A_HI, sb + A_LO, sb + BQK_HI, sb + BQK_LO, lane, gw, d);
            // bias in-place: nt<8 -> Q (+bq), nt>=8 -> K (+bk)
#pragma unroll
            for (int nt = 0; nt < 16; ++nt) {
                int c = (nt & 7) * 8 + l4 * 2;
                float b0 = bias_sm[(nt < 8 ? 0 : 64) + c];
                float b1 = bias_sm[(nt < 8 ? 0 : 64) + c + 1];
                d[nt][0] += b0; d[nt][1] += b1;
                d[nt][2] += b0; d[nt][3] += b1;
            }
#pragma unroll
            for (int pi = 0; pi < 2; ++pi) {
                float sc[8];
#pragma unroll
                for (int s = 0; s < 8; ++s) {
                    int src = s * 4 + l4;
                    float a = 0.f;
#pragma unroll
                    for (int nt = 0; nt < 8; ++nt)
#pragma unroll
                        for (int j = 0; j < 2; ++j)
                            a += d[nt][pi * 2 + j] *
                                 __shfl_sync(0xffffffffu, d[8 + nt][pi * 2 + j], src);
                    a += __shfl_xor_sync(0xffffffffu, a, 1);
                    a += __shfl_xor_sync(0xffffffffu, a, 2);
                    sc[s] = a * 0.125f;           // 1/sqrt(64)
                }
                float mx = sc[0];
#pragma unroll
                for (int s = 1; s < 8; ++s) mx = fmaxf(mx, sc[s]);
                float sum = 0.f, e[8];
#pragma unroll
                for (int s = 0; s < 8; ++s) { e[s] = __expf(sc[s] - mx); sum += e[s]; }
                float inv = 1.f / sum;
                if (l4 == 0) {
                    int p = gw * 2 + pi;
#pragma unroll
                    for (int s = 0; s < 8; ++s)
                        Ssm[(p * 8 + lg) * 8 + s] = e[s] * inv;
                }
            }
        } else {
            do_gemm(sb + A_HI, sb + A_LO, sb + BV_HI, sb + BV_LO, lane, gw, d);
        }
        __syncthreads();

        // ---- V warps: attn@V + bv -> outst (rotated for coalesced IO) ----
        if (wid >= 4) {
            const int p0 = gw * 2, p1 = p0 + 1;
            float attn0[8], attn1[8];
#pragma unroll
            for (int s = 0; s < 8; ++s) {
                attn0[s] = Ssm[(p0 * 8 + lg) * 8 + s];
                attn1[s] = Ssm[(p1 * 8 + lg) * 8 + s];
            }
#pragma unroll
            for (int nt = 0; nt < 16; ++nt)
#pragma unroll
                for (int j = 0; j < 2; ++j) {
                    int c = nt * 8 + l4 * 2 + j;
                    float o0 = bias_sm[128 + c], o1 = o0;
#pragma unroll
                    for (int s = 0; s < 8; ++s) {
                        int src = s * 4 + l4;
                        o0 += attn0[s] * __shfl_sync(0xffffffffu, d[nt][j], src);
                        o1 += attn1[s] * __shfl_sync(0xffffffffu, d[nt][2 + j], src);
                    }
                    int rot = (c >> 1) & 7;
                    int base = (lg * 128 + c) * 10 + lg * 2;
                    outst[base + ((p0 + rot) & 7)] = o0;
                    outst[base + ((p1 + rot) & 7)] = o1;
                }
        }
        __syncthreads();

        // ---- coalesced gmem store: out[b,t,e,pix0+p] ---------------------
        {
            float* ob = out + (size_t)(tt / 1152) * (kT * kC * kHW) +
                        (size_t)(tt % 1152) * kPIX;
#pragma unroll 4
            for (int it2 = 0; it2 < 32; ++it2) {
                int q = it2 * 32 + tcb;           // t*128 + e
                int t = q >> 7, c = q & 127, rot = (c >> 1) & 7;
                ob[(size_t)q * kHW + p8] =
                    outst[q * 10 + t * 2 + ((p8 + rot) & 7)];
            }
        }
        __syncthreads();    // protect outst/scratch before next phase 1
    }
}

extern "C" void kernel_launch(void* const* d_in, const int* in_sizes, int n_in,
                              void* d_out, int out_size)
{
    const float* x  = (const float*)d_in[0];
    const float* Wq = (const float*)d_in[1];
    const float* bq = (const float*)d_in[2];
    const float* Wk = (const float*)d_in[3];
    const float* bk = (const float*)d_in[4];
    const float* Wv = (const float*)d_in[5];
    const float* bv = (const float*)d_in[6];
    float* out = (float*)d_out;

    const int B = in_sizes[0] / (kT * kC * kHW);
    const int total = B * (kHW / kPIX);           // 8-pixel tiles
    cudaFuncSetAttribute(ta_pers, cudaFuncAttributeMaxDynamicSharedMemorySize,
                         kSMEM);
    ta_pers<<<kGRID, kTHREADS, kSMEM>>>(x, Wq, bq, Wk, bk, Wv, bv, out, total);
}